// round 15
// baseline (speedup 1.0000x reference)
#include <cuda_runtime.h>
#include <cstdint>
#include <math.h>

// Problem dims (fixed by setup_inputs)
#define Bdim 2048
#define Vdim 4096
#define Hdim 2048
#define Ldim 10
#define KCD  10

// Eigen gebp panel depths (validated bit-exact in R12/R13)
#define BK_K4096 320
#define BK_K2048 248

typedef unsigned long long u64;

// Scratch (device globals: no runtime allocation allowed)
__device__ float g_h[(size_t)Bdim * Hdim];
__device__ float g_v[(size_t)Bdim * Vdim];
__device__ float g_hT[(size_t)Hdim * Bdim];
__device__ float g_vT[(size_t)Vdim * Bdim];
__device__ float g_w1t[(size_t)Vdim * Hdim];
__device__ unsigned char g_labidx[Bdim];

// ---------------------------------------------------------------------------
// Packed f32x2 ops (per-lane IEEE .rn, bit-identical to scalar; R13-validated)
// ---------------------------------------------------------------------------
__device__ __forceinline__ u64 pack2(float lo, float hi)
{
  u64 r; asm("mov.b64 %0, {%1, %2};" : "=l"(r) : "f"(lo), "f"(hi)); return r;
}
__device__ __forceinline__ void unpack2(u64 v, float& lo, float& hi)
{
  asm("mov.b64 {%0, %1}, %2;" : "=f"(lo), "=f"(hi) : "l"(v));
}
__device__ __forceinline__ u64 ffma2(u64 a, u64 b, u64 c)
{
  u64 d; asm("fma.rn.f32x2 %0, %1, %2, %3;" : "=l"(d) : "l"(a), "l"(b), "l"(c));
  return d;
}
__device__ __forceinline__ u64 fadd2(u64 a, u64 b)
{
  u64 d; asm("add.rn.f32x2 %0, %1, %2;" : "=l"(d) : "l"(a), "l"(b));
  return d;
}

// cp.async 16B (LDGSTS), L2-cached
__device__ __forceinline__ void cpa16(void* dst, const void* src)
{
  uint32_t d = (uint32_t)__cvta_generic_to_shared(dst);
  asm volatile("cp.async.cg.shared.global [%0], [%1], 16;" :: "r"(d), "l"(src));
}
#define CP_COMMIT() asm volatile("cp.async.commit_group;")
#define CP_WAIT0()  asm volatile("cp.async.wait_group 0;")

// ---------------------------------------------------------------------------
// threefry2x32 (exact JAX implementation)
// ---------------------------------------------------------------------------
__host__ __device__ __forceinline__ void threefry2x32(
    uint32_t k0, uint32_t k1, uint32_t x0, uint32_t x1,
    uint32_t& o0, uint32_t& o1)
{
  uint32_t ks2 = k0 ^ k1 ^ 0x1BD11BDAu;
#define TFR(r) x0 += x1; x1 = (x1 << (r)) | (x1 >> (32 - (r))); x1 ^= x0;
  x0 += k0; x1 += k1;
  TFR(13) TFR(15) TFR(26) TFR(6)
  x0 += k1;  x1 += ks2 + 1u;
  TFR(17) TFR(29) TFR(16) TFR(24)
  x0 += ks2; x1 += k0 + 2u;
  TFR(13) TFR(15) TFR(26) TFR(6)
  x0 += k0;  x1 += k1 + 3u;
  TFR(17) TFR(29) TFR(16) TFR(24)
  x0 += k1;  x1 += ks2 + 4u;
  TFR(13) TFR(15) TFR(26) TFR(6)
  x0 += ks2; x1 += k0 + 5u;
#undef TFR
  o0 = x0; o1 = x1;
}

// Partitionable threefry random_bits (validated bit-exact R4/R12)
__device__ __forceinline__ float jax_uniform_fold(uint32_t k0, uint32_t k1,
                                                  uint32_t idx)
{
  uint32_t o0, o1;
  threefry2x32(k0, k1, 0u, idx, o0, o1);
  uint32_t bits = o0 ^ o1;
  return __uint_as_float((bits >> 9) | 0x3f800000u) - 1.0f;
}

// ---------------------------------------------------------------------------
// XLA logistic (validated bit-exact R4/R12)
// ---------------------------------------------------------------------------
__device__ __forceinline__ float xla_tanh_f32(float x)
{
  float ax = fabsf(x);
  float xc = fminf(fmaxf(x, -9.0f), 9.0f);
  float x2 = __fmul_rn(xc, xc);
  float p = -2.76076847742355e-16f;
  p = __fadd_rn(2.00018790482477e-13f, __fmul_rn(x2, p));
  p = __fadd_rn(-8.60467152213735e-11f, __fmul_rn(x2, p));
  p = __fadd_rn(5.12229709037114e-08f, __fmul_rn(x2, p));
  p = __fadd_rn(1.48572235717979e-05f, __fmul_rn(x2, p));
  p = __fadd_rn(6.37261928875436e-04f, __fmul_rn(x2, p));
  p = __fadd_rn(4.89352455891786e-03f, __fmul_rn(x2, p));
  float num = __fmul_rn(xc, p);
  float q = 1.19825839466702e-06f;
  q = __fadd_rn(1.18534705686654e-04f, __fmul_rn(x2, q));
  q = __fadd_rn(2.26843463243900e-03f, __fmul_rn(x2, q));
  q = __fadd_rn(4.89352518554385e-03f, __fmul_rn(x2, q));
  float t = __fdiv_rn(num, q);
  return (ax < 0.0004f) ? x : t;
}

__device__ __forceinline__ float xla_sigmoid(float x)
{
  float t = xla_tanh_f32(__fmul_rn(0.5f, x));
  return __fadd_rn(0.5f, __fmul_rn(0.5f, t));
}

__device__ __forceinline__ float log_f32_cr(float x)
{
  return (float)log((double)x);
}

// ---------------------------------------------------------------------------
// label -> index
// ---------------------------------------------------------------------------
__global__ void labidx_kernel(const float* __restrict__ label,
                              unsigned char* __restrict__ idx)
{
  int b = blockIdx.x * blockDim.x + threadIdx.x;
  if (b < Bdim) {
    int best = 0;
    float bvv = label[b * Ldim];
    #pragma unroll
    for (int l = 1; l < Ldim; l++) {
      float x = label[b * Ldim + l];
      if (x > bvv) { bvv = x; best = l; }
    }
    idx[b] = (unsigned char)best;
  }
}

// ---------------------------------------------------------------------------
// Tiled transpose: in [R][C] -> out [C][R]. R, C multiples of 32.
// ---------------------------------------------------------------------------
__global__ void transpose_kernel(const float* __restrict__ in,
                                 float* __restrict__ out, int R, int C)
{
  __shared__ float tile[32][33];
  int c0 = blockIdx.x * 32, r0 = blockIdx.y * 32;
  #pragma unroll
  for (int i = threadIdx.y; i < 32; i += 8)
    tile[i][threadIdx.x] = in[(size_t)(r0 + i) * C + c0 + threadIdx.x];
  __syncthreads();
  #pragma unroll
  for (int i = threadIdx.y; i < 32; i += 8)
    out[(size_t)(c0 + i) * R + r0 + threadIdx.x] = tile[threadIdx.x][i];
}

// ---------------------------------------------------------------------------
// Fused GEMM + sigmoid + Bernoulli sample.
// Both operands k-major in GMEM: AT=[K][M], Bk=[K][N] (pre-transposed host-
// side where needed). cp.async double-buffered pipeline, one barrier/tile.
// Compute loop (FFMA2 + Eigen kc panels) is instruction-identical to R13 ->
// bit-exact reduction order preserved.
// ---------------------------------------------------------------------------
template<bool ADDLAB>
__global__ void __launch_bounds__(256)
gemm_sample(const float* __restrict__ AT, const float* __restrict__ Bk,
            const float* __restrict__ bias, const float* __restrict__ W2,
            const unsigned char* __restrict__ labidx,
            uint32_t rk0, uint32_t rk1,
            int M, int N, int K, int bk,
            float* __restrict__ outp, float* __restrict__ out2)
{
  __shared__ __align__(16) float As[2][16][132];
  __shared__ __align__(16) float Bs[2][16][132];
  const int tid = threadIdx.x;
  const int tx = tid & 15, ty = tid >> 4;
  const int n0 = blockIdx.x * 128, m0 = blockIdx.y * 128;

  // cp.async chunk coords: 512 16B-chunks per 16x128 tile, 2 per thread
  const int kr0 = tid >> 5, c0 = tid & 31;       // rows 0..7
  const int kr1 = kr0 + 8, c1 = c0;              // rows 8..15

  u64 tot2[8][4];
  u64 accp2[8][4];
  #pragma unroll
  for (int i = 0; i < 8; i++)
    #pragma unroll
    for (int q = 0; q < 4; q++) { tot2[i][q] = 0ull; accp2[i][q] = 0ull; }

  const int T = K >> 4;

  // prologue: tile 0 -> buf 0
  {
    cpa16(&As[0][kr0][c0 * 4], &AT[(size_t)kr0 * M + m0 + c0 * 4]);
    cpa16(&As[0][kr1][c1 * 4], &AT[(size_t)kr1 * M + m0 + c1 * 4]);
    cpa16(&Bs[0][kr0][c0 * 4], &Bk[(size_t)kr0 * N + n0 + c0 * 4]);
    cpa16(&Bs[0][kr1][c1 * 4], &Bk[(size_t)kr1 * N + n0 + c1 * 4]);
    CP_COMMIT();
  }

  for (int t = 0; t < T; t++) {
    const int cur = t & 1;
    const int k0 = t << 4;

    CP_WAIT0();           // tile t copies (this thread) complete
    __syncthreads();      // all threads' tile-t data visible; buf[nxt] free

    if (t + 1 < T) {      // issue tile t+1 into the other buffer
      const int nxt = cur ^ 1;
      const int kn = k0 + 16;
      cpa16(&As[nxt][kr0][c0 * 4], &AT[(size_t)(kn + kr0) * M + m0 + c0 * 4]);
      cpa16(&As[nxt][kr1][c1 * 4], &AT[(size_t)(kn + kr1) * M + m0 + c1 * 4]);
      cpa16(&Bs[nxt][kr0][c0 * 4], &Bk[(size_t)(kn + kr0) * N + n0 + c0 * 4]);
      cpa16(&Bs[nxt][kr1][c1 * 4], &Bk[(size_t)(kn + kr1) * N + n0 + c1 * 4]);
      CP_COMMIT();
    }

    // compute tile t (instruction-identical to R13)
    const int rem = k0 % bk;
    const int bkk = (rem == 0) ? 0 : (bk - rem);  // >=16 means none this tile
    #pragma unroll
    for (int kk = 0; kk < 16; kk++) {
      if (kk == bkk && (k0 + kk) > 0) {
        #pragma unroll
        for (int i = 0; i < 8; i++)
          #pragma unroll
          for (int q = 0; q < 4; q++) {
            tot2[i][q] = fadd2(tot2[i][q], accp2[i][q]);
            accp2[i][q] = 0ull;
          }
      }
      float ra[8];
      *(float4*)&ra[0] = *(const float4*)&As[cur][kk][ty * 4];
      *(float4*)&ra[4] = *(const float4*)&As[cur][kk][64 + ty * 4];
      u64 rb2[4];
      {
        const u64* b0 = (const u64*)&Bs[cur][kk][tx * 4];
        const u64* b1 = (const u64*)&Bs[cur][kk][64 + tx * 4];
        rb2[0] = b0[0]; rb2[1] = b0[1];
        rb2[2] = b1[0]; rb2[3] = b1[1];
      }
      #pragma unroll
      for (int i = 0; i < 8; i++) {
        u64 ra2 = pack2(ra[i], ra[i]);
        #pragma unroll
        for (int q = 0; q < 4; q++)
          accp2[i][q] = ffma2(ra2, rb2[q], accp2[i][q]);
      }
    }
  }
  // final partial panel
  #pragma unroll
  for (int i = 0; i < 8; i++)
    #pragma unroll
    for (int q = 0; q < 4; q++)
      tot2[i][q] = fadd2(tot2[i][q], accp2[i][q]);

  #pragma unroll
  for (int i = 0; i < 8; i++) {
    int gm = m0 + ((i < 4) ? (ty * 4 + i) : (64 + ty * 4 + i - 4));
    int lab = ADDLAB ? (int)labidx[gm] : 0;
    float tot[8];
    #pragma unroll
    for (int q = 0; q < 4; q++) unpack2(tot2[i][q], tot[2 * q], tot[2 * q + 1]);
    #pragma unroll
    for (int j = 0; j < 8; j++) {
      int gn = n0 + ((j < 4) ? (tx * 4 + j) : (64 + tx * 4 + j - 4));
      float x = tot[j];
      if (ADDLAB) x = __fadd_rn(x, W2[gn * Ldim + lab]);  // (m1 + m2) ...
      x = __fadd_rn(x, bias[gn]);                          // ... + bias
      float p = xla_sigmoid(x);
      uint32_t jj = (uint32_t)gm * (uint32_t)N + (uint32_t)gn;
      float u = jax_uniform_fold(rk0, rk1, jj);
      float smp = (u < p) ? 1.0f : 0.0f;
      outp[jj] = smp;
      if (out2) out2[jj] = smp;
    }
  }
}

// ---------------------------------------------------------------------------
// categorical (validated bit-exact in R12)
// ---------------------------------------------------------------------------
__global__ void __launch_bounds__(32)
cat_kernel(const float* __restrict__ hm,
           const float* __restrict__ W2,
           const float* __restrict__ bv2,
           uint32_t rk0, uint32_t rk1,
           unsigned char* __restrict__ labidx,
           float* __restrict__ out2)
{
  const int b = blockIdx.x;
  const int l = threadIdx.x;
  const float TINY = 1.1754943508222875e-38f;

  float z = -INFINITY;
  if (l < Ldim) {
    const float* hrow = hm + (size_t)b * Hdim;
    float tot = 0.f, accp = 0.f;
    for (int k = 0; k < Hdim; k++) {
      if (k > 0 && (k % BK_K2048) == 0) { tot = __fadd_rn(tot, accp); accp = 0.f; }
      accp = fmaf(hrow[k], W2[k * Ldim + l], accp);
    }
    tot = __fadd_rn(tot, accp);
    float logit = __fadd_rn(tot, bv2[l]);
    uint32_t jj = (uint32_t)b * Ldim + (uint32_t)l;
    float u = jax_uniform_fold(rk0, rk1, jj);
    u = __fadd_rn(u, TINY);
    u = fmaxf(u, TINY);
    float lg1 = log_f32_cr(u);
    float lg2 = log_f32_cr(-lg1);
    float g = -lg2;
    z = __fadd_rn(logit, g);
  }
  int bi = l;
  #pragma unroll
  for (int off = 16; off > 0; off >>= 1) {
    float oz = __shfl_down_sync(0xffffffffu, z, off);
    int obi = __shfl_down_sync(0xffffffffu, bi, off);
    if (oz > z || (oz == z && obi < bi)) { z = oz; bi = obi; }
  }
  if (l == 0) {
    labidx[b] = (unsigned char)bi;
    if (out2) {
      #pragma unroll
      for (int q = 0; q < Ldim; q++)
        out2[(size_t)b * Ldim + q] = (q == bi) ? 1.0f : 0.0f;
    }
  }
}

// ---------------------------------------------------------------------------
// host key schedule: JAX fold-like split (partitionable default)
// ---------------------------------------------------------------------------
static inline void jax_split_fold(uint32_t k0, uint32_t k1, int n,
                                  uint32_t out[][2])
{
  for (int i = 0; i < n; i++)
    threefry2x32(k0, k1, 0u, (uint32_t)i, out[i][0], out[i][1]);
}

extern "C" void kernel_launch(void* const* d_in, const int* in_sizes, int n_in,
                              void* d_out, int out_size)
{
  const float* v     = (const float*)d_in[0];
  const float* label = (const float*)d_in[1];
  const float* W1    = (const float*)d_in[2];
  const float* W2    = (const float*)d_in[3];
  const float* bv1   = (const float*)d_in[4];
  const float* bv2   = (const float*)d_in[5];
  const float* bh    = (const float*)d_in[6];

  float* out      = (float*)d_out;
  float* out_hpos = out;
  float* out_vneg = out_hpos + (size_t)Bdim * Hdim;
  float* out_lneg = out_vneg + (size_t)Bdim * Vdim;
  float* out_hneg = out_lneg + (size_t)Bdim * Ldim;

  float *dh, *dv, *dhT, *dvT, *dw1t; unsigned char* dli;
  cudaGetSymbolAddress((void**)&dh, g_h);
  cudaGetSymbolAddress((void**)&dv, g_v);
  cudaGetSymbolAddress((void**)&dhT, g_hT);
  cudaGetSymbolAddress((void**)&dvT, g_vT);
  cudaGetSymbolAddress((void**)&dw1t, g_w1t);
  cudaGetSymbolAddress((void**)&dli, g_labidx);

  uint32_t s2[2][2];
  jax_split_fold(0u, 42u, 2, s2);
  uint32_t key0 = s2[0][0], key1 = s2[0][1];
  uint32_t kp0 = s2[1][0], kp1 = s2[1][1];

  labidx_kernel<<<(Bdim + 255) / 256, 256>>>(label, dli);

  dim3 tb(32, 8);
  // W1 [H][V] -> w1t [V][H]
  transpose_kernel<<<dim3(Vdim / 32, Hdim / 32), tb>>>(W1, dw1t, Hdim, Vdim);
  // v [B][V] -> vT [V][B]
  transpose_kernel<<<dim3(Vdim / 32, Bdim / 32), tb>>>(v, dvT, Bdim, Vdim);

  dim3 blk(256);
  dim3 grdH(Hdim / 128, Bdim / 128);
  dim3 grdV(Vdim / 128, Bdim / 128);

  // positive phase: h_pos = bern(kp, sigmoid(v@W1^T + label@W2^T + bh))
  // C[B][H]: AT = vT [V][B], Bk = w1t [V][H], K=V
  gemm_sample<true><<<grdH, blk>>>(dvT, dw1t, bh, W2, dli, kp0, kp1,
                                   Bdim, Hdim, Vdim, BK_K4096, dh, out_hpos);
  // h [B][H] -> hT [H][B]
  transpose_kernel<<<dim3(Hdim / 32, Bdim / 32), tb>>>(dh, dhT, Bdim, Hdim);

  for (int t = 0; t < KCD; t++) {
    uint32_t ks[4][2];
    jax_split_fold(key0, key1, 4, ks);
    key0 = ks[0][0]; key1 = ks[0][1];
    const bool last = (t == KCD - 1);

    // v_s = bern(k1, sigmoid(h@W1 + bv1)): AT = hT [H][B], Bk = W1 [H][V], K=H
    gemm_sample<false><<<grdV, blk>>>(dhT, W1, bv1, nullptr, nullptr,
                                      ks[1][0], ks[1][1],
                                      Bdim, Vdim, Hdim, BK_K2048,
                                      dv, last ? out_vneg : nullptr);
    // v_s [B][V] -> vT [V][B]
    transpose_kernel<<<dim3(Vdim / 32, Bdim / 32), tb>>>(dv, dvT, Bdim, Vdim);

    // lab_s = one_hot(categorical(k2, h@W2 + bv2))  (reads current h)
    cat_kernel<<<Bdim, 32>>>(dh, W2, bv2, ks[2][0], ks[2][1], dli,
                             last ? out_lneg : nullptr);

    // h_new = bern(k3, sigmoid(v_s@W1^T + lab_s@W2^T + bh)):
    // AT = vT [V][B], Bk = w1t [V][H], K=V
    gemm_sample<true><<<grdH, blk>>>(dvT, dw1t, bh, W2, dli,
                                     ks[3][0], ks[3][1],
                                     Bdim, Hdim, Vdim, BK_K4096,
                                     last ? out_hneg : dh, nullptr);
    if (!last)
      transpose_kernel<<<dim3(Hdim / 32, Bdim / 32), tb>>>(dh, dhT, Bdim, Hdim);
  }
}

// round 16
// speedup vs baseline: 1.8449x; 1.8449x over previous
#include <cuda_runtime.h>
#include <cstdint>
#include <math.h>

// Problem dims (fixed by setup_inputs)
#define Bdim 2048
#define Vdim 4096
#define Hdim 2048
#define Ldim 10
#define KCD  10

// Eigen gebp panel depths (validated bit-exact in R12/R13)
#define BK_K4096 320
#define BK_K2048 248

typedef unsigned long long u64;

// Scratch (device globals: no runtime allocation allowed)
__device__ float g_h[(size_t)Bdim * Hdim];
__device__ float g_v[(size_t)Bdim * Vdim];
__device__ unsigned char g_labidx[Bdim];

// ---------------------------------------------------------------------------
// Packed f32x2 ops (per-lane IEEE .rn, bit-identical to scalar; R13-validated)
// ---------------------------------------------------------------------------
__device__ __forceinline__ u64 pack2(float lo, float hi)
{
  u64 r; asm("mov.b64 %0, {%1, %2};" : "=l"(r) : "f"(lo), "f"(hi)); return r;
}
__device__ __forceinline__ void unpack2(u64 v, float& lo, float& hi)
{
  asm("mov.b64 {%0, %1}, %2;" : "=f"(lo), "=f"(hi) : "l"(v));
}
__device__ __forceinline__ u64 ffma2(u64 a, u64 b, u64 c)
{
  u64 d; asm("fma.rn.f32x2 %0, %1, %2, %3;" : "=l"(d) : "l"(a), "l"(b), "l"(c));
  return d;
}
__device__ __forceinline__ u64 fadd2(u64 a, u64 b)
{
  u64 d; asm("add.rn.f32x2 %0, %1, %2;" : "=l"(d) : "l"(a), "l"(b));
  return d;
}

// ---------------------------------------------------------------------------
// threefry2x32 (exact JAX implementation)
// ---------------------------------------------------------------------------
__host__ __device__ __forceinline__ void threefry2x32(
    uint32_t k0, uint32_t k1, uint32_t x0, uint32_t x1,
    uint32_t& o0, uint32_t& o1)
{
  uint32_t ks2 = k0 ^ k1 ^ 0x1BD11BDAu;
#define TFR(r) x0 += x1; x1 = (x1 << (r)) | (x1 >> (32 - (r))); x1 ^= x0;
  x0 += k0; x1 += k1;
  TFR(13) TFR(15) TFR(26) TFR(6)
  x0 += k1;  x1 += ks2 + 1u;
  TFR(17) TFR(29) TFR(16) TFR(24)
  x0 += ks2; x1 += k0 + 2u;
  TFR(13) TFR(15) TFR(26) TFR(6)
  x0 += k0;  x1 += k1 + 3u;
  TFR(17) TFR(29) TFR(16) TFR(24)
  x0 += k1;  x1 += ks2 + 4u;
  TFR(13) TFR(15) TFR(26) TFR(6)
  x0 += ks2; x1 += k0 + 5u;
#undef TFR
  o0 = x0; o1 = x1;
}

// Partitionable threefry random_bits (validated bit-exact R4/R12)
__device__ __forceinline__ float jax_uniform_fold(uint32_t k0, uint32_t k1,
                                                  uint32_t idx)
{
  uint32_t o0, o1;
  threefry2x32(k0, k1, 0u, idx, o0, o1);
  uint32_t bits = o0 ^ o1;
  return __uint_as_float((bits >> 9) | 0x3f800000u) - 1.0f;
}

// ---------------------------------------------------------------------------
// XLA logistic (validated bit-exact R4/R12)
// ---------------------------------------------------------------------------
__device__ __forceinline__ float xla_tanh_f32(float x)
{
  float ax = fabsf(x);
  float xc = fminf(fmaxf(x, -9.0f), 9.0f);
  float x2 = __fmul_rn(xc, xc);
  float p = -2.76076847742355e-16f;
  p = __fadd_rn(2.00018790482477e-13f, __fmul_rn(x2, p));
  p = __fadd_rn(-8.60467152213735e-11f, __fmul_rn(x2, p));
  p = __fadd_rn(5.12229709037114e-08f, __fmul_rn(x2, p));
  p = __fadd_rn(1.48572235717979e-05f, __fmul_rn(x2, p));
  p = __fadd_rn(6.37261928875436e-04f, __fmul_rn(x2, p));
  p = __fadd_rn(4.89352455891786e-03f, __fmul_rn(x2, p));
  float num = __fmul_rn(xc, p);
  float q = 1.19825839466702e-06f;
  q = __fadd_rn(1.18534705686654e-04f, __fmul_rn(x2, q));
  q = __fadd_rn(2.26843463243900e-03f, __fmul_rn(x2, q));
  q = __fadd_rn(4.89352518554385e-03f, __fmul_rn(x2, q));
  float t = __fdiv_rn(num, q);
  return (ax < 0.0004f) ? x : t;
}

__device__ __forceinline__ float xla_sigmoid(float x)
{
  float t = xla_tanh_f32(__fmul_rn(0.5f, x));
  return __fadd_rn(0.5f, __fmul_rn(0.5f, t));
}

__device__ __forceinline__ float log_f32_cr(float x)
{
  return (float)log((double)x);
}

// ---------------------------------------------------------------------------
// label -> index
// ---------------------------------------------------------------------------
__global__ void labidx_kernel(const float* __restrict__ label,
                              unsigned char* __restrict__ idx)
{
  int b = blockIdx.x * blockDim.x + threadIdx.x;
  if (b < Bdim) {
    int best = 0;
    float bvv = label[b * Ldim];
    #pragma unroll
    for (int l = 1; l < Ldim; l++) {
      float x = label[b * Ldim + l];
      if (x > bvv) { bvv = x; best = l; }
    }
    idx[b] = (unsigned char)best;
  }
}

// ---------------------------------------------------------------------------
// Fused GEMM + sigmoid + Bernoulli sample. BM=64 x BN=128 tile, 256 threads,
// 4m x 8n per thread (accs = 32 u64 -> <=128 regs -> 2 blocks/SM). Pipeline =
// R13's known-good single-buffer LDG->STS, 2 barriers/tile; cross-block
// interleaving on the SM hides the exposed load latency.
// Per-element reduction: sequential ascending-k fmaf chains with Eigen kc
// panels — identical to R13 (bit-frozen).
// ---------------------------------------------------------------------------
template<bool TRANSB, bool ADDLAB>
__global__ void __launch_bounds__(256, 2)
gemm_sample(const float* __restrict__ A, const float* __restrict__ Bm,
            const float* __restrict__ bias, const float* __restrict__ W2,
            const unsigned char* __restrict__ labidx,
            uint32_t rk0, uint32_t rk1,
            int M, int N, int K, int bk,
            float* __restrict__ outp, float* __restrict__ out2)
{
  __shared__ __align__(16) float As[16][68];    // 16 k x 64 m (+pad)
  __shared__ __align__(16) float Bs[16][132];   // 16 k x 128 n (+pad)
  const int tid = threadIdx.x;
  const int tx = tid & 15, ty = tid >> 4;       // tx: n-group, ty: m-group
  const int n0 = blockIdx.x * 128, m0 = blockIdx.y * 64;

  u64 tot2[4][4];    // cross-panel sum, packed pairs over j (4 m-rows)
  u64 accp2[4][4];   // current panel register chain
  #pragma unroll
  for (int i = 0; i < 4; i++)
    #pragma unroll
    for (int q = 0; q < 4; q++) { tot2[i][q] = 0ull; accp2[i][q] = 0ull; }

  for (int k0 = 0; k0 < K; k0 += 16) {
    // A tile: 64 rows x 16 k, transposed into As[k][m]; 1 float4/thread
    {
      int row = tid >> 2, q = tid & 3;
      const float4 f = *(const float4*)&A[(size_t)(m0 + row) * K + k0 + q * 4];
      As[q * 4 + 0][row] = f.x; As[q * 4 + 1][row] = f.y;
      As[q * 4 + 2][row] = f.z; As[q * 4 + 3][row] = f.w;
    }
    if (TRANSB) {
      #pragma unroll
      for (int s = tid; s < 512; s += 256) {
        int row = s >> 2, q = s & 3;
        const float4 f = *(const float4*)&Bm[(size_t)(n0 + row) * K + k0 + q * 4];
        Bs[q * 4 + 0][row] = f.x; Bs[q * 4 + 1][row] = f.y;
        Bs[q * 4 + 2][row] = f.z; Bs[q * 4 + 3][row] = f.w;
      }
    } else {
      #pragma unroll
      for (int s = tid; s < 512; s += 256) {
        int kr = s >> 5, c4 = s & 31;
        const float4 f = *(const float4*)&Bm[(size_t)(k0 + kr) * N + n0 + c4 * 4];
        *(float4*)&Bs[kr][c4 * 4] = f;
      }
    }
    __syncthreads();
    // panel boundary inside this 16-wide tile (if any): kk with (k0+kk)%bk==0
    const int rem = k0 % bk;
    const int bkk = (rem == 0) ? 0 : (bk - rem);  // >=16 means none this tile
    #pragma unroll
    for (int kk = 0; kk < 16; kk++) {
      if (kk == bkk && (k0 + kk) > 0) {
        #pragma unroll
        for (int i = 0; i < 4; i++)
          #pragma unroll
          for (int q = 0; q < 4; q++) {
            tot2[i][q] = fadd2(tot2[i][q], accp2[i][q]);
            accp2[i][q] = 0ull;
          }
      }
      float ra[4];
      *(float4*)&ra[0] = *(const float4*)&As[kk][ty * 4];
      u64 rb2[4];
      {
        const u64* b0 = (const u64*)&Bs[kk][tx * 4];
        const u64* b1 = (const u64*)&Bs[kk][64 + tx * 4];
        rb2[0] = b0[0]; rb2[1] = b0[1];
        rb2[2] = b1[0]; rb2[3] = b1[1];
      }
      #pragma unroll
      for (int i = 0; i < 4; i++) {
        u64 ra2 = pack2(ra[i], ra[i]);
        #pragma unroll
        for (int q = 0; q < 4; q++)
          accp2[i][q] = ffma2(ra2, rb2[q], accp2[i][q]);
      }
    }
    __syncthreads();
  }
  // final partial panel
  #pragma unroll
  for (int i = 0; i < 4; i++)
    #pragma unroll
    for (int q = 0; q < 4; q++)
      tot2[i][q] = fadd2(tot2[i][q], accp2[i][q]);

  #pragma unroll
  for (int i = 0; i < 4; i++) {
    int gm = m0 + ty * 4 + i;
    int lab = ADDLAB ? (int)labidx[gm] : 0;
    float tot[8];
    #pragma unroll
    for (int q = 0; q < 4; q++) unpack2(tot2[i][q], tot[2 * q], tot[2 * q + 1]);
    #pragma unroll
    for (int j = 0; j < 8; j++) {
      int gn = n0 + ((j < 4) ? (tx * 4 + j) : (64 + tx * 4 + j - 4));
      float x = tot[j];
      if (ADDLAB) x = __fadd_rn(x, W2[gn * Ldim + lab]);  // (m1 + m2) ...
      x = __fadd_rn(x, bias[gn]);                          // ... + bias
      float p = xla_sigmoid(x);
      uint32_t jj = (uint32_t)gm * (uint32_t)N + (uint32_t)gn;
      float u = jax_uniform_fold(rk0, rk1, jj);
      float smp = (u < p) ? 1.0f : 0.0f;
      outp[jj] = smp;
      if (out2) out2[jj] = smp;
    }
  }
}

// ---------------------------------------------------------------------------
// categorical (validated bit-exact in R12)
// ---------------------------------------------------------------------------
__global__ void __launch_bounds__(32)
cat_kernel(const float* __restrict__ hm,
           const float* __restrict__ W2,
           const float* __restrict__ bv2,
           uint32_t rk0, uint32_t rk1,
           unsigned char* __restrict__ labidx,
           float* __restrict__ out2)
{
  const int b = blockIdx.x;
  const int l = threadIdx.x;
  const float TINY = 1.1754943508222875e-38f;

  float z = -INFINITY;
  if (l < Ldim) {
    const float* hrow = hm + (size_t)b * Hdim;
    float tot = 0.f, accp = 0.f;
    for (int k = 0; k < Hdim; k++) {
      if (k > 0 && (k % BK_K2048) == 0) { tot = __fadd_rn(tot, accp); accp = 0.f; }
      accp = fmaf(hrow[k], W2[k * Ldim + l], accp);
    }
    tot = __fadd_rn(tot, accp);
    float logit = __fadd_rn(tot, bv2[l]);
    uint32_t jj = (uint32_t)b * Ldim + (uint32_t)l;
    float u = jax_uniform_fold(rk0, rk1, jj);
    u = __fadd_rn(u, TINY);
    u = fmaxf(u, TINY);
    float lg1 = log_f32_cr(u);
    float lg2 = log_f32_cr(-lg1);
    float g = -lg2;
    z = __fadd_rn(logit, g);
  }
  int bi = l;
  #pragma unroll
  for (int off = 16; off > 0; off >>= 1) {
    float oz = __shfl_down_sync(0xffffffffu, z, off);
    int obi = __shfl_down_sync(0xffffffffu, bi, off);
    if (oz > z || (oz == z && obi < bi)) { z = oz; bi = obi; }
  }
  if (l == 0) {
    labidx[b] = (unsigned char)bi;
    if (out2) {
      #pragma unroll
      for (int q = 0; q < Ldim; q++)
        out2[(size_t)b * Ldim + q] = (q == bi) ? 1.0f : 0.0f;
    }
  }
}

// ---------------------------------------------------------------------------
// host key schedule: JAX fold-like split (partitionable default)
// ---------------------------------------------------------------------------
static inline void jax_split_fold(uint32_t k0, uint32_t k1, int n,
                                  uint32_t out[][2])
{
  for (int i = 0; i < n; i++)
    threefry2x32(k0, k1, 0u, (uint32_t)i, out[i][0], out[i][1]);
}

extern "C" void kernel_launch(void* const* d_in, const int* in_sizes, int n_in,
                              void* d_out, int out_size)
{
  const float* v     = (const float*)d_in[0];
  const float* label = (const float*)d_in[1];
  const float* W1    = (const float*)d_in[2];
  const float* W2    = (const float*)d_in[3];
  const float* bv1   = (const float*)d_in[4];
  const float* bv2   = (const float*)d_in[5];
  const float* bh    = (const float*)d_in[6];

  float* out      = (float*)d_out;
  float* out_hpos = out;
  float* out_vneg = out_hpos + (size_t)Bdim * Hdim;
  float* out_lneg = out_vneg + (size_t)Bdim * Vdim;
  float* out_hneg = out_lneg + (size_t)Bdim * Ldim;

  float *dh, *dv; unsigned char* dli;
  cudaGetSymbolAddress((void**)&dh, g_h);
  cudaGetSymbolAddress((void**)&dv, g_v);
  cudaGetSymbolAddress((void**)&dli, g_labidx);

  uint32_t s2[2][2];
  jax_split_fold(0u, 42u, 2, s2);
  uint32_t key0 = s2[0][0], key1 = s2[0][1];
  uint32_t kp0 = s2[1][0], kp1 = s2[1][1];

  labidx_kernel<<<(Bdim + 255) / 256, 256>>>(label, dli);

  dim3 blk(256);
  dim3 grdH(Hdim / 128, Bdim / 64);
  dim3 grdV(Vdim / 128, Bdim / 64);

  // positive phase: h_pos = bern(kp, sigmoid(v@W1^T + label@W2^T + bh)), K=4096
  gemm_sample<true, true><<<grdH, blk>>>(v, W1, bh, W2, dli, kp0, kp1,
                                         Bdim, Hdim, Vdim, BK_K4096,
                                         dh, out_hpos);

  for (int t = 0; t < KCD; t++) {
    uint32_t ks[4][2];
    jax_split_fold(key0, key1, 4, ks);
    key0 = ks[0][0]; key1 = ks[0][1];
    const bool last = (t == KCD - 1);

    // v_s = bern(k1, sigmoid(h@W1 + bv1)), K=2048 -> kc=248
    gemm_sample<false, false><<<grdV, blk>>>(dh, W1, bv1, nullptr, nullptr,
                                             ks[1][0], ks[1][1],
                                             Bdim, Vdim, Hdim, BK_K2048,
                                             dv, last ? out_vneg : nullptr);
    // lab_s = one_hot(categorical(k2, h@W2 + bv2)), K=2048 -> kc=248
    cat_kernel<<<Bdim, 32>>>(dh, W2, bv2, ks[2][0], ks[2][1], dli,
                             last ? out_lneg : nullptr);
    // h_new = bern(k3, sigmoid(v_s@W1^T + lab_s@W2^T + bh)), K=4096 -> kc=320
    gemm_sample<true, true><<<grdH, blk>>>(dv, W1, bh, W2, dli,
                                           ks[3][0], ks[3][1],
                                           Bdim, Hdim, Vdim, BK_K4096,
                                           last ? out_hneg : dh, nullptr);
  }
}

// round 17
// speedup vs baseline: 1.9671x; 1.0662x over previous
#include <cuda_runtime.h>
#include <cstdint>
#include <math.h>

// Problem dims (fixed by setup_inputs)
#define Bdim 2048
#define Vdim 4096
#define Hdim 2048
#define Ldim 10
#define KCD  10

// Eigen gebp panel depths (validated bit-exact in R12/R13/R16)
#define BK_K4096 320
#define BK_K2048 248

typedef unsigned long long u64;

// Scratch (device globals: no runtime allocation allowed)
__device__ float g_h[(size_t)Bdim * Hdim];
__device__ float g_v[(size_t)Bdim * Vdim];
__device__ unsigned char g_labidx[Bdim];

// ---------------------------------------------------------------------------
// Packed f32x2 ops (per-lane IEEE .rn, bit-identical to scalar; validated)
// ---------------------------------------------------------------------------
__device__ __forceinline__ u64 pack2(float lo, float hi)
{
  u64 r; asm("mov.b64 %0, {%1, %2};" : "=l"(r) : "f"(lo), "f"(hi)); return r;
}
__device__ __forceinline__ void unpack2(u64 v, float& lo, float& hi)
{
  asm("mov.b64 {%0, %1}, %2;" : "=f"(lo), "=f"(hi) : "l"(v));
}
__device__ __forceinline__ u64 ffma2(u64 a, u64 b, u64 c)
{
  u64 d; asm("fma.rn.f32x2 %0, %1, %2, %3;" : "=l"(d) : "l"(a), "l"(b), "l"(c));
  return d;
}
__device__ __forceinline__ u64 fadd2(u64 a, u64 b)
{
  u64 d; asm("add.rn.f32x2 %0, %1, %2;" : "=l"(d) : "l"(a), "l"(b));
  return d;
}

// ---------------------------------------------------------------------------
// threefry2x32 (exact JAX implementation)
// ---------------------------------------------------------------------------
__host__ __device__ __forceinline__ void threefry2x32(
    uint32_t k0, uint32_t k1, uint32_t x0, uint32_t x1,
    uint32_t& o0, uint32_t& o1)
{
  uint32_t ks2 = k0 ^ k1 ^ 0x1BD11BDAu;
#define TFR(r) x0 += x1; x1 = (x1 << (r)) | (x1 >> (32 - (r))); x1 ^= x0;
  x0 += k0; x1 += k1;
  TFR(13) TFR(15) TFR(26) TFR(6)
  x0 += k1;  x1 += ks2 + 1u;
  TFR(17) TFR(29) TFR(16) TFR(24)
  x0 += ks2; x1 += k0 + 2u;
  TFR(13) TFR(15) TFR(26) TFR(6)
  x0 += k0;  x1 += k1 + 3u;
  TFR(17) TFR(29) TFR(16) TFR(24)
  x0 += k1;  x1 += ks2 + 4u;
  TFR(13) TFR(15) TFR(26) TFR(6)
  x0 += ks2; x1 += k0 + 5u;
#undef TFR
  o0 = x0; o1 = x1;
}

// Partitionable threefry random_bits (validated bit-exact R4/R12)
__device__ __forceinline__ float jax_uniform_fold(uint32_t k0, uint32_t k1,
                                                  uint32_t idx)
{
  uint32_t o0, o1;
  threefry2x32(k0, k1, 0u, idx, o0, o1);
  uint32_t bits = o0 ^ o1;
  return __uint_as_float((bits >> 9) | 0x3f800000u) - 1.0f;
}

// ---------------------------------------------------------------------------
// XLA logistic (validated bit-exact R4/R12)
// ---------------------------------------------------------------------------
__device__ __forceinline__ float xla_tanh_f32(float x)
{
  float ax = fabsf(x);
  float xc = fminf(fmaxf(x, -9.0f), 9.0f);
  float x2 = __fmul_rn(xc, xc);
  float p = -2.76076847742355e-16f;
  p = __fadd_rn(2.00018790482477e-13f, __fmul_rn(x2, p));
  p = __fadd_rn(-8.60467152213735e-11f, __fmul_rn(x2, p));
  p = __fadd_rn(5.12229709037114e-08f, __fmul_rn(x2, p));
  p = __fadd_rn(1.48572235717979e-05f, __fmul_rn(x2, p));
  p = __fadd_rn(6.37261928875436e-04f, __fmul_rn(x2, p));
  p = __fadd_rn(4.89352455891786e-03f, __fmul_rn(x2, p));
  float num = __fmul_rn(xc, p);
  float q = 1.19825839466702e-06f;
  q = __fadd_rn(1.18534705686654e-04f, __fmul_rn(x2, q));
  q = __fadd_rn(2.26843463243900e-03f, __fmul_rn(x2, q));
  q = __fadd_rn(4.89352518554385e-03f, __fmul_rn(x2, q));
  float t = __fdiv_rn(num, q);
  return (ax < 0.0004f) ? x : t;
}

__device__ __forceinline__ float xla_sigmoid(float x)
{
  float t = xla_tanh_f32(__fmul_rn(0.5f, x));
  return __fadd_rn(0.5f, __fmul_rn(0.5f, t));
}

__device__ __forceinline__ float log_f32_cr(float x)
{
  return (float)log((double)x);
}

// ---------------------------------------------------------------------------
// label -> index
// ---------------------------------------------------------------------------
__global__ void labidx_kernel(const float* __restrict__ label,
                              unsigned char* __restrict__ idx)
{
  int b = blockIdx.x * blockDim.x + threadIdx.x;
  if (b < Bdim) {
    int best = 0;
    float bvv = label[b * Ldim];
    #pragma unroll
    for (int l = 1; l < Ldim; l++) {
      float x = label[b * Ldim + l];
      if (x > bvv) { bvv = x; best = l; }
    }
    idx[b] = (unsigned char)best;
  }
}

// ---------------------------------------------------------------------------
// Warp-level categorical for one batch row (identical math to R12-validated
// cat_kernel): logits = h@W2 + bv2 with kc=248 panels, gumbel-argmax with
// correctly-rounded log, first-max tie-break.
// ---------------------------------------------------------------------------
__device__ __forceinline__ void cat_row(
    int b, int lane,
    const float* __restrict__ hm, const float* __restrict__ W2,
    const float* __restrict__ bv2, uint32_t rk0, uint32_t rk1,
    unsigned char* __restrict__ labidx, float* __restrict__ out2)
{
  const float TINY = 1.1754943508222875e-38f;
  float z = -INFINITY;
  if (lane < Ldim) {
    const float* hrow = hm + (size_t)b * Hdim;
    float tot = 0.f, accp = 0.f;
    for (int k = 0; k < Hdim; k++) {
      if (k > 0 && (k % BK_K2048) == 0) { tot = __fadd_rn(tot, accp); accp = 0.f; }
      accp = fmaf(hrow[k], W2[k * Ldim + lane], accp);
    }
    tot = __fadd_rn(tot, accp);
    float logit = __fadd_rn(tot, bv2[lane]);
    uint32_t jj = (uint32_t)b * Ldim + (uint32_t)lane;
    float u = jax_uniform_fold(rk0, rk1, jj);
    u = __fadd_rn(u, TINY);
    u = fmaxf(u, TINY);
    float lg1 = log_f32_cr(u);
    float lg2 = log_f32_cr(-lg1);
    float g = -lg2;
    z = __fadd_rn(logit, g);
  }
  int bi = lane;
  #pragma unroll
  for (int off = 16; off > 0; off >>= 1) {
    float oz = __shfl_down_sync(0xffffffffu, z, off);
    int obi = __shfl_down_sync(0xffffffffu, bi, off);
    if (oz > z || (oz == z && obi < bi)) { z = oz; bi = obi; }
  }
  if (lane == 0) {
    labidx[b] = (unsigned char)bi;
    if (out2) {
      #pragma unroll
      for (int q = 0; q < Ldim; q++)
        out2[(size_t)b * Ldim + q] = (q == bi) ? 1.0f : 0.0f;
    }
  }
}

// ---------------------------------------------------------------------------
// Fused GEMM + sigmoid + Bernoulli sample (R16 layout: BM=64 x BN=128, 256
// threads, 2 blocks/SM) with OPTIONAL appended cat blocks: blockIdx.x >=
// catBase handles categorical rows (8 warps x 1 row), overlapping the
// independent cat work with the GEMM within one launch.
// Per-element reduction: sequential ascending-k fmaf chains with Eigen kc
// panels — unchanged from R16 (bit-frozen).
// ---------------------------------------------------------------------------
template<bool TRANSB, bool ADDLAB>
__global__ void __launch_bounds__(256, 2)
gemm_sample(const float* __restrict__ A, const float* __restrict__ Bm,
            const float* __restrict__ bias, const float* __restrict__ W2,
            const unsigned char* __restrict__ labidx,
            uint32_t rk0, uint32_t rk1,
            int M, int N, int K, int bk, int nTilesX, int catBase,
            float* __restrict__ outp, float* __restrict__ out2,
            // cat args (used only by blocks >= catBase)
            const float* __restrict__ cat_h, const float* __restrict__ bv2,
            uint32_t ck0, uint32_t ck1,
            unsigned char* __restrict__ cat_labidx,
            float* __restrict__ cat_out2)
{
  if ((int)blockIdx.x >= catBase) {
    int wid = threadIdx.x >> 5, lane = threadIdx.x & 31;
    int b = ((int)blockIdx.x - catBase) * 8 + wid;
    if (b < Bdim)
      cat_row(b, lane, cat_h, W2, bv2, ck0, ck1, cat_labidx, cat_out2);
    return;
  }

  __shared__ __align__(16) float As[16][68];    // 16 k x 64 m (+pad)
  __shared__ __align__(16) float Bs[16][132];   // 16 k x 128 n (+pad)
  const int tid = threadIdx.x;
  const int tx = tid & 15, ty = tid >> 4;       // tx: n-group, ty: m-group
  const int bx = (int)blockIdx.x % nTilesX, by = (int)blockIdx.x / nTilesX;
  const int n0 = bx * 128, m0 = by * 64;

  u64 tot2[4][4];    // cross-panel sum, packed pairs over j (4 m-rows)
  u64 accp2[4][4];   // current panel register chain
  #pragma unroll
  for (int i = 0; i < 4; i++)
    #pragma unroll
    for (int q = 0; q < 4; q++) { tot2[i][q] = 0ull; accp2[i][q] = 0ull; }

  for (int k0 = 0; k0 < K; k0 += 16) {
    // A tile: 64 rows x 16 k, transposed into As[k][m]; 1 float4/thread
    {
      int row = tid >> 2, q = tid & 3;
      const float4 f = *(const float4*)&A[(size_t)(m0 + row) * K + k0 + q * 4];
      As[q * 4 + 0][row] = f.x; As[q * 4 + 1][row] = f.y;
      As[q * 4 + 2][row] = f.z; As[q * 4 + 3][row] = f.w;
    }
    if (TRANSB) {
      #pragma unroll
      for (int s = tid; s < 512; s += 256) {
        int row = s >> 2, q = s & 3;
        const float4 f = *(const float4*)&Bm[(size_t)(n0 + row) * K + k0 + q * 4];
        Bs[q * 4 + 0][row] = f.x; Bs[q * 4 + 1][row] = f.y;
        Bs[q * 4 + 2][row] = f.z; Bs[q * 4 + 3][row] = f.w;
      }
    } else {
      #pragma unroll
      for (int s = tid; s < 512; s += 256) {
        int kr = s >> 5, c4 = s & 31;
        const float4 f = *(const float4*)&Bm[(size_t)(k0 + kr) * N + n0 + c4 * 4];
        *(float4*)&Bs[kr][c4 * 4] = f;
      }
    }
    __syncthreads();
    // panel boundary inside this 16-wide tile (if any): kk with (k0+kk)%bk==0
    const int rem = k0 % bk;
    const int bkk = (rem == 0) ? 0 : (bk - rem);  // >=16 means none this tile
    #pragma unroll
    for (int kk = 0; kk < 16; kk++) {
      if (kk == bkk && (k0 + kk) > 0) {
        #pragma unroll
        for (int i = 0; i < 4; i++)
          #pragma unroll
          for (int q = 0; q < 4; q++) {
            tot2[i][q] = fadd2(tot2[i][q], accp2[i][q]);
            accp2[i][q] = 0ull;
          }
      }
      float ra[4];
      *(float4*)&ra[0] = *(const float4*)&As[kk][ty * 4];
      u64 rb2[4];
      {
        const u64* b0 = (const u64*)&Bs[kk][tx * 4];
        const u64* b1 = (const u64*)&Bs[kk][64 + tx * 4];
        rb2[0] = b0[0]; rb2[1] = b0[1];
        rb2[2] = b1[0]; rb2[3] = b1[1];
      }
      #pragma unroll
      for (int i = 0; i < 4; i++) {
        u64 ra2 = pack2(ra[i], ra[i]);
        #pragma unroll
        for (int q = 0; q < 4; q++)
          accp2[i][q] = ffma2(ra2, rb2[q], accp2[i][q]);
      }
    }
    __syncthreads();
  }
  // final partial panel
  #pragma unroll
  for (int i = 0; i < 4; i++)
    #pragma unroll
    for (int q = 0; q < 4; q++)
      tot2[i][q] = fadd2(tot2[i][q], accp2[i][q]);

  #pragma unroll
  for (int i = 0; i < 4; i++) {
    int gm = m0 + ty * 4 + i;
    int lab = ADDLAB ? (int)labidx[gm] : 0;
    float tot[8];
    #pragma unroll
    for (int q = 0; q < 4; q++) unpack2(tot2[i][q], tot[2 * q], tot[2 * q + 1]);
    #pragma unroll
    for (int j = 0; j < 8; j++) {
      int gn = n0 + ((j < 4) ? (tx * 4 + j) : (64 + tx * 4 + j - 4));
      float x = tot[j];
      if (ADDLAB) x = __fadd_rn(x, W2[gn * Ldim + lab]);  // (m1 + m2) ...
      x = __fadd_rn(x, bias[gn]);                          // ... + bias
      float p = xla_sigmoid(x);
      uint32_t jj = (uint32_t)gm * (uint32_t)N + (uint32_t)gn;
      float u = jax_uniform_fold(rk0, rk1, jj);
      float smp = (u < p) ? 1.0f : 0.0f;
      outp[jj] = smp;
      if (out2) out2[jj] = smp;
    }
  }
}

// ---------------------------------------------------------------------------
// host key schedule: JAX fold-like split (partitionable default)
// ---------------------------------------------------------------------------
static inline void jax_split_fold(uint32_t k0, uint32_t k1, int n,
                                  uint32_t out[][2])
{
  for (int i = 0; i < n; i++)
    threefry2x32(k0, k1, 0u, (uint32_t)i, out[i][0], out[i][1]);
}

extern "C" void kernel_launch(void* const* d_in, const int* in_sizes, int n_in,
                              void* d_out, int out_size)
{
  const float* v     = (const float*)d_in[0];
  const float* label = (const float*)d_in[1];
  const float* W1    = (const float*)d_in[2];
  const float* W2    = (const float*)d_in[3];
  const float* bv1   = (const float*)d_in[4];
  const float* bv2   = (const float*)d_in[5];
  const float* bh    = (const float*)d_in[6];

  float* out      = (float*)d_out;
  float* out_hpos = out;
  float* out_vneg = out_hpos + (size_t)Bdim * Hdim;
  float* out_lneg = out_vneg + (size_t)Bdim * Vdim;
  float* out_hneg = out_lneg + (size_t)Bdim * Ldim;

  float *dh, *dv; unsigned char* dli;
  cudaGetSymbolAddress((void**)&dh, g_h);
  cudaGetSymbolAddress((void**)&dv, g_v);
  cudaGetSymbolAddress((void**)&dli, g_labidx);

  uint32_t s2[2][2];
  jax_split_fold(0u, 42u, 2, s2);
  uint32_t key0 = s2[0][0], key1 = s2[0][1];
  uint32_t kp0 = s2[1][0], kp1 = s2[1][1];

  labidx_kernel<<<(Bdim + 255) / 256, 256>>>(label, dli);

  dim3 blk(256);
  const int tilesH_x = Hdim / 128, tilesH = tilesH_x * (Bdim / 64);   // 512
  const int tilesV_x = Vdim / 128, tilesV = tilesV_x * (Bdim / 64);   // 1024
  const int catBlocks = Bdim / 8;                                     // 256

  // positive phase: h_pos = bern(kp, sigmoid(v@W1^T + label@W2^T + bh)), K=4096
  gemm_sample<true, true><<<tilesH, blk>>>(
      v, W1, bh, W2, dli, kp0, kp1,
      Bdim, Hdim, Vdim, BK_K4096, tilesH_x, tilesH,
      dh, out_hpos, nullptr, nullptr, 0u, 0u, nullptr, nullptr);

  for (int t = 0; t < KCD; t++) {
    uint32_t ks[4][2];
    jax_split_fold(key0, key1, 4, ks);
    key0 = ks[0][0]; key1 = ks[0][1];
    const bool last = (t == KCD - 1);

    // FUSED: v_s = bern(k1, sigmoid(h@W1 + bv1)) [K=2048, kc=248]
    //        + cat rows: lab_s = one_hot(categorical(k2, h@W2 + bv2))
    // (both read only h from the previous step -> independent)
    gemm_sample<false, false><<<tilesV + catBlocks, blk>>>(
        dh, W1, bv1, W2, nullptr, ks[1][0], ks[1][1],
        Bdim, Vdim, Hdim, BK_K2048, tilesV_x, tilesV,
        dv, last ? out_vneg : nullptr,
        dh, bv2, ks[2][0], ks[2][1], dli, last ? out_lneg : nullptr);

    // h_new = bern(k3, sigmoid(v_s@W1^T + lab_s@W2^T + bh)), K=4096 -> kc=320
    gemm_sample<true, true><<<tilesH, blk>>>(
        dv, W1, bh, W2, dli, ks[3][0], ks[3][1],
        Bdim, Hdim, Vdim, BK_K4096, tilesH_x, tilesH,
        last ? out_hneg : dh, nullptr,
        nullptr, nullptr, 0u, 0u, nullptr, nullptr);
  }
}